// round 15
// baseline (speedup 1.0000x reference)
#include <cuda_runtime.h>
#include <cstdint>
#include <cstddef>

// Problem constants (fixed by reference: N=256, C=2048, H=16, W=8, K=13)
#define KPT   13
#define HW_   128
#define CCH   2048
#define NBAT  256
#define TC    128     // channels per CTA tile
#define NTHR  256

typedef unsigned long long ull;

__device__ __forceinline__ void upk2(ull v, float &lo, float &hi) {
    asm("mov.b64 {%0, %1}, %2;" : "=f"(lo), "=f"(hi) : "l"(v));
}
__device__ __forceinline__ void ffma2(ull &d, ull a, ull b) {
    asm("fma.rn.f32x2 %0, %1, %2, %0;" : "+l"(d) : "l"(a), "l"(b));
}
__device__ __forceinline__ void fadd2(ull &d, ull a) {
    asm("add.rn.f32x2 %0, %0, %1;" : "+l"(d) : "l"(a));
}
__device__ __forceinline__ float fold2(ull v) {
    float lo, hi; upk2(v, lo, hi); return lo + hi;
}
__device__ __forceinline__ void cp16(uint32_t dst, const void* src) {
    asm volatile("cp.async.cg.shared.global [%0], [%1], 16;\n" :: "r"(dst), "l"(src));
}

// Dynamic smem:
//   [0, 65536)       feat 128ch x 32 f4, XOR-swizzled (aliased by red buf)
//   [65536, 72192)   score 13 x 32 f4
#define SMEM_BYTES 72192
extern __shared__ unsigned char smem_raw[];

// ======================================================================
// CTA = (n, 128-channel tile). 8 warps = 2 k-groups x 4 hw-slices.
// Lane cp owns 4 channels {2cp, 2cp+1, 2cp+64, 2cp+65} (same swizzle),
// hw slice [sl*32, sl*32+32), k-subset kg (kg0: k<7, kg1: k in [7,13)
// + global sum/max). Each score LDS.128 now feeds 8 FFMA2 (4 channels)
// -> score broadcast wavefronts halved per channel vs 2ch/lane.
// CTA 0 additionally computes the confidence output (hidden under loads).
// ======================================================================
__global__ __launch_bounds__(NTHR, 3) void horeid_feat_kernel(
    const float* __restrict__ feat,
    const float* __restrict__ sco,
    const float* __restrict__ kc,
    float* __restrict__ out)
{
    float4* sfeat = reinterpret_cast<float4*>(smem_raw);
    const float4* ssco = reinterpret_cast<const float4*>(smem_raw + 65536);
    float2* red2 = reinterpret_cast<float2*>(smem_raw);   // alias after sync
    float*  red  = reinterpret_cast<float*>(smem_raw);

    const int t  = threadIdx.x;
    const int n  = blockIdx.x >> 4;          // 16 tiles of 128 ch per n
    const int c0 = (blockIdx.x & 15) * TC;
    const int kg = t >> 7;                   // k-group (warp-uniform)
    const int sl = (t >> 5) & 3;             // hw slice (warp-uniform)
    const int cp = t & 31;                   // lane: 4 channels
    const int kbase = kg * 7;
    const int kn    = kg ? 6 : 7;

    const uint32_t fb = (uint32_t)__cvta_generic_to_shared(smem_raw);

    // ---- async load scoremap (416 f4) + feat tile (4096 f4) ----
    const float4* g_sco = reinterpret_cast<const float4*>(sco + (size_t)n * (KPT * HW_));
    for (int g = t; g < KPT * 32; g += NTHR)
        cp16(fb + 65536u + (uint32_t)g * 16u, g_sco + g);

    const float4* g_feat = reinterpret_cast<const float4*>(
        feat + ((size_t)n * CCH + c0) * HW_);
#pragma unroll
    for (int i = 0; i < 16; ++i) {
        int g  = t + i * NTHR;
        int ch = g >> 5, cl = g & 31;
        cp16(fb + (uint32_t)(ch * 32 + (cl ^ ((ch >> 1) & 7))) * 16u, g_feat + g);
    }
    asm volatile("cp.async.commit_group;\n");

    // ---- CTA 0: confidence output (overlapped with its own loads) ----
    if (blockIdx.x == 0) {
        const float* r = kc + t * KPT;
        float v[KPT];
        float s = 0.0f;
#pragma unroll
        for (int i = 0; i < KPT; ++i) { v[i] = r[i]; s += fabsf(v[i]); }
        s = fmaxf(s, 1e-12f);
        const float inv = 1.0f / s;
        float* o = out + (size_t)NBAT * 14 * CCH + t * 14;
#pragma unroll
        for (int i = 0; i < KPT; ++i) o[i] = v[i] * inv;
        o[KPT] = 1.0f;
    }

    asm volatile("cp.async.wait_group 0;\n");
    __syncthreads();

    // ---- compute ----
    ull a0[7], a1[7], b0a[7], b1a[7];       // 4 channel rows x kn
#pragma unroll
    for (int kk = 0; kk < 7; ++kk) { a0[kk] = a1[kk] = b0a[kk] = b1a[kk] = 0ull; }
    ull s0 = 0ull, s1 = 0ull, s2 = 0ull, s3 = 0ull;   // kg1: spatial sums
    float m0 = -3.402823466e38f, m1 = m0, m2 = m0, m3 = m0;

    const float4* fr0 = &sfeat[(2 * cp) * 32];        // row 2cp
    const float4* fr1 = fr0 + 32;                     // row 2cp+1
    const float4* fr2 = fr0 + 64 * 32;                // row 2cp+64
    const float4* fr3 = fr2 + 32;                     // row 2cp+65
    const int swz = cp & 7;                           // same for all 4 rows

#pragma unroll
    for (int jj = 0; jj < 8; ++jj) {
        const int j    = sl * 8 + jj;        // f4 column (warp-uniform)
        const int colx = j ^ swz;

        float4 f0 = fr0[colx];
        float4 f1 = fr1[colx];
        float4 f2 = fr2[colx];
        float4 f3 = fr3[colx];
        ull p00 = reinterpret_cast<ull*>(&f0)[0], p01 = reinterpret_cast<ull*>(&f0)[1];
        ull p10 = reinterpret_cast<ull*>(&f1)[0], p11 = reinterpret_cast<ull*>(&f1)[1];
        ull p20 = reinterpret_cast<ull*>(&f2)[0], p21 = reinterpret_cast<ull*>(&f2)[1];
        ull p30 = reinterpret_cast<ull*>(&f3)[0], p31 = reinterpret_cast<ull*>(&f3)[1];

        if (kg == 1) {                        // warp-uniform: global branch on kg1
            fadd2(s0, p00); fadd2(s0, p01);
            fadd2(s1, p10); fadd2(s1, p11);
            fadd2(s2, p20); fadd2(s2, p21);
            fadd2(s3, p30); fadd2(s3, p31);
            m0 = fmaxf(m0, fmaxf(fmaxf(f0.x, f0.y), fmaxf(f0.z, f0.w)));
            m1 = fmaxf(m1, fmaxf(fmaxf(f1.x, f1.y), fmaxf(f1.z, f1.w)));
            m2 = fmaxf(m2, fmaxf(fmaxf(f2.x, f2.y), fmaxf(f2.z, f2.w)));
            m3 = fmaxf(m3, fmaxf(fmaxf(f3.x, f3.y), fmaxf(f3.z, f3.w)));
        }

#pragma unroll
        for (int kk = 0; kk < 7; ++kk) {
            if (kk < kn) {                    // warp-uniform predicate
                float4 sv = ssco[(kbase + kk) * 32 + j];   // uniform broadcast
                ull sc01 = reinterpret_cast<const ull*>(&sv)[0];
                ull sc23 = reinterpret_cast<const ull*>(&sv)[1];
                ffma2(a0[kk],  sc01, p00); ffma2(a0[kk],  sc23, p01);
                ffma2(a1[kk],  sc01, p10); ffma2(a1[kk],  sc23, p11);
                ffma2(b0a[kk], sc01, p20); ffma2(b0a[kk], sc23, p21);
                ffma2(b1a[kk], sc01, p30); ffma2(b1a[kk], sc23, p31);
            }
        }
    }
    __syncthreads();   // all sfeat reads done -> alias as reduction buffer

    // ---- stage partials: red[slot*512 + sl*128 + ch]
    //      pair A at ch = 2cp (float2), pair B at ch = 2cp+64 ----
#pragma unroll
    for (int kk = 0; kk < 7; ++kk) {
        if (kk < kn) {
            const int base = ((kbase + kk) * 4 + sl) * 64;
            red2[base + cp]      = make_float2(fold2(a0[kk]),  fold2(a1[kk]));
            red2[base + 32 + cp] = make_float2(fold2(b0a[kk]), fold2(b1a[kk]));
        }
    }
    if (kg == 1) {
        const int bs = (13 * 4 + sl) * 64;
        red2[bs + cp]      = make_float2(fold2(s0), fold2(s1));
        red2[bs + 32 + cp] = make_float2(fold2(s2), fold2(s3));
        const int bm = (14 * 4 + sl) * 64;
        red2[bm + cp]      = make_float2(m0, m1);
        red2[bm + 32 + cp] = make_float2(m2, m3);
    }
    __syncthreads();

    // ---- fold 4 slices, write coalesced (14*128 = 1792 outputs) ----
    float* ob = out + (size_t)n * (14 * CCH) + c0;
#pragma unroll
    for (int it = 0; it < 7; ++it) {
        const int idx  = t + it * NTHR;
        const int slot = idx >> 7, ch = idx & 127;
        if (slot < 13) {
            float v = red[slot * 512 + ch]       + red[slot * 512 + 128 + ch]
                    + red[slot * 512 + 256 + ch] + red[slot * 512 + 384 + ch];
            ob[slot * CCH + ch] = v;
        } else {
            float v = red[13 * 512 + ch]       + red[13 * 512 + 128 + ch]
                    + red[13 * 512 + 256 + ch] + red[13 * 512 + 384 + ch];
            float m = fmaxf(fmaxf(red[14 * 512 + ch],       red[14 * 512 + 128 + ch]),
                            fmaxf(red[14 * 512 + 256 + ch], red[14 * 512 + 384 + ch]));
            ob[13 * CCH + ch] = v * (1.0f / 128.0f) + m;
        }
    }
}

// ======================================================================
extern "C" void kernel_launch(void* const* d_in, const int* in_sizes, int n_in,
                              void* d_out, int out_size)
{
    const float* feat = nullptr;
    const float* sco  = nullptr;
    const float* kc   = nullptr;
    for (int i = 0; i < n_in; ++i) {
        if (in_sizes[i] == NBAT * CCH * HW_)      feat = (const float*)d_in[i];
        else if (in_sizes[i] == NBAT * KPT * HW_) sco  = (const float*)d_in[i];
        else if (in_sizes[i] == NBAT * KPT)       kc   = (const float*)d_in[i];
    }
    float* out = (float*)d_out;

    cudaFuncSetAttribute(horeid_feat_kernel,
                         cudaFuncAttributeMaxDynamicSharedMemorySize, SMEM_BYTES);

    horeid_feat_kernel<<<NBAT * 16, NTHR, SMEM_BYTES>>>(feat, sco, kc, out);
    (void)out_size;
}

// round 16
// speedup vs baseline: 1.9209x; 1.9209x over previous
#include <cuda_runtime.h>
#include <cstdint>
#include <cstddef>

// Problem constants (fixed by reference: N=256, C=2048, H=16, W=8, K=13)
#define KPT   13
#define HW_   128
#define CCH   2048
#define NBAT  256
#define TC    64      // channels per CTA
#define NTHR  256

typedef unsigned long long ull;

__device__ __forceinline__ void upk2(ull v, float &lo, float &hi) {
    asm("mov.b64 {%0, %1}, %2;" : "=f"(lo), "=f"(hi) : "l"(v));
}
__device__ __forceinline__ void ffma2(ull &d, ull a, ull b) {
    asm("fma.rn.f32x2 %0, %1, %2, %0;" : "+l"(d) : "l"(a), "l"(b));
}
__device__ __forceinline__ void fadd2(ull &d, ull a) {
    asm("add.rn.f32x2 %0, %0, %1;" : "+l"(d) : "l"(a));
}
__device__ __forceinline__ void cp16(uint32_t dst, const void* src) {
    asm volatile("cp.async.cg.shared.global [%0], [%1], 16;\n" :: "r"(dst), "l"(src));
}

// Static smem (39.4 KB < 48 KB default — no attribute call needed):
//   sfeat: feat 64ch x 32 f4 swizzled (aliased by red buf)
//   ssco:  score 13 x 32 f4
struct SmemLayout {
    float4 sfeat[TC * 32];
    float4 ssco[KPT * 32];
};

// ======================================================================
// CTA = (n, 64-channel tile). 8 warps: warps 0-3 -> k in [0,7),
// warps 4-7 -> k in [7,13). Thread (kg, sl, cp):
//   channels {2cp, 2cp+1}, hw slice [sl*32, sl*32+32), k-subset kg.
// f32x2 lanes = adjacent hw pairs straight from LDS.128 register pairs.
// CTA 0 additionally computes the confidence output, hidden under its
// own cp.async load phase (no separate kernel launch).
// ======================================================================
__global__ __launch_bounds__(NTHR, 4) void horeid_feat_kernel(
    const float* __restrict__ feat,
    const float* __restrict__ sco,
    const float* __restrict__ kc,
    float* __restrict__ out)
{
    __shared__ SmemLayout sm;
    float4* sfeat = sm.sfeat;
    float4* ssco  = sm.ssco;
    float2* red2  = reinterpret_cast<float2*>(sm.sfeat);   // alias after sync
    float*  red   = reinterpret_cast<float*>(sm.sfeat);

    const int t  = threadIdx.x;
    const int n  = blockIdx.x >> 5;          // 32 tiles per batch row
    const int c0 = (blockIdx.x & 31) * TC;
    const int kg = t >> 7;                   // k-group (warp-uniform)
    const int sl = (t >> 5) & 3;             // hw slice   (warp-uniform)
    const int cp = t & 31;                   // channel pair (lane)
    const int kbase = kg * 7;
    const int kn    = kg ? 6 : 7;

    const uint32_t fbase = (uint32_t)__cvta_generic_to_shared(sm.sfeat);
    const uint32_t scb   = (uint32_t)__cvta_generic_to_shared(sm.ssco);

    // ---- async load scoremap (416 f4) ----
    const float4* g_sco = reinterpret_cast<const float4*>(sco + (size_t)n * (KPT * HW_));
    for (int g = t; g < KPT * 32; g += NTHR)
        cp16(scb + (uint32_t)g * 16u, g_sco + g);

    // ---- async load feat tile (2048 f4), swizzle col ^ ((ch>>1)&7) ----
    const float4* g_feat = reinterpret_cast<const float4*>(
        feat + ((size_t)n * CCH + c0) * HW_);
#pragma unroll
    for (int i = 0; i < 8; ++i) {
        int g  = t + i * NTHR;
        int ch = g >> 5, cl = g & 31;
        cp16(fbase + (uint32_t)(ch * 32 + (cl ^ ((ch >> 1) & 7))) * 16u, g_feat + g);
    }
    asm volatile("cp.async.commit_group;\n");

    // ---- CTA 0: confidence output (hidden under the load phase) ----
    if (blockIdx.x == 0) {
        const float* r = kc + t * KPT;       // thread t -> batch row t
        float v[KPT];
        float s = 0.0f;
#pragma unroll
        for (int i = 0; i < KPT; ++i) { v[i] = r[i]; s += fabsf(v[i]); }
        s = fmaxf(s, 1e-12f);
        const float inv = 1.0f / s;
        float* o = out + (size_t)NBAT * 14 * CCH + t * 14;
#pragma unroll
        for (int i = 0; i < KPT; ++i) o[i] = v[i] * inv;
        o[KPT] = 1.0f;
    }

    asm volatile("cp.async.wait_group 0;\n");
    __syncthreads();

    ull acc0[7], acc1[7];
#pragma unroll
    for (int kk = 0; kk < 7; ++kk) { acc0[kk] = 0ull; acc1[kk] = 0ull; }
    ull sum0 = 0ull, sum1 = 0ull;
    float mx0 = -3.402823466e38f, mx1 = mx0;

    const float4* fr0 = &sfeat[(2 * cp) * 32];
    const float4* fr1 = fr0 + 32;
    const int swz = cp & 7;

#pragma unroll
    for (int jj = 0; jj < 8; ++jj) {
        const int j    = sl * 8 + jj;        // f4 column (warp-uniform)
        const int colx = j ^ swz;

        float4 f0 = fr0[colx];
        float4 f1 = fr1[colx];
        ull a0 = reinterpret_cast<ull*>(&f0)[0];
        ull a1 = reinterpret_cast<ull*>(&f0)[1];
        ull b0 = reinterpret_cast<ull*>(&f1)[0];
        ull b1 = reinterpret_cast<ull*>(&f1)[1];

        if (kg == 0) {                        // warp-uniform branch
            fadd2(sum0, a0); fadd2(sum0, a1);
            fadd2(sum1, b0); fadd2(sum1, b1);
            mx0 = fmaxf(mx0, fmaxf(fmaxf(f0.x, f0.y), fmaxf(f0.z, f0.w)));
            mx1 = fmaxf(mx1, fmaxf(fmaxf(f1.x, f1.y), fmaxf(f1.z, f1.w)));
        }

#pragma unroll
        for (int kk = 0; kk < 7; ++kk) {
            if (kk < kn) {                    // warp-uniform predicate
                float4 sv = ssco[(kbase + kk) * 32 + j];   // uniform broadcast
                ull s01 = reinterpret_cast<ull*>(&sv)[0];
                ull s23 = reinterpret_cast<ull*>(&sv)[1];
                ffma2(acc0[kk], s01, a0); ffma2(acc0[kk], s23, a1);
                ffma2(acc1[kk], s01, b0); ffma2(acc1[kk], s23, b1);
            }
        }
    }
    __syncthreads();   // done reading sfeat; alias as reduction buffer

    // ---- stage partials: red2[slot*128 + sl*32 + cp] = (ch0, ch1) ----
    // slots 0..12 local k, 13 spatial sum, 14 spatial max
#pragma unroll
    for (int kk = 0; kk < 7; ++kk) {
        if (kk < kn) {
            float l0, h0, l1, h1;
            upk2(acc0[kk], l0, h0);
            upk2(acc1[kk], l1, h1);
            red2[(kbase + kk) * 128 + sl * 32 + cp] = make_float2(l0 + h0, l1 + h1);
        }
    }
    if (kg == 0) {
        float l0, h0, l1, h1;
        upk2(sum0, l0, h0);
        upk2(sum1, l1, h1);
        red2[13 * 128 + sl * 32 + cp] = make_float2(l0 + h0, l1 + h1);
        red2[14 * 128 + sl * 32 + cp] = make_float2(mx0, mx1);
    }
    __syncthreads();

    // ---- fold 4 slices, write coalesced (14*64 = 896 outputs) ----
    float* ob = out + (size_t)n * (14 * CCH) + c0;
#pragma unroll
    for (int it = 0; it < 4; ++it) {
        const int idx = t + it * NTHR;
        if (idx < 14 * TC) {
            const int slot = idx >> 6, ch = idx & 63;
            if (slot < 13) {
                float v = red[slot * 256 + ch]       + red[slot * 256 + 64 + ch]
                        + red[slot * 256 + 128 + ch] + red[slot * 256 + 192 + ch];
                ob[slot * CCH + ch] = v;
            } else {
                float v = red[13 * 256 + ch]       + red[13 * 256 + 64 + ch]
                        + red[13 * 256 + 128 + ch] + red[13 * 256 + 192 + ch];
                float m = fmaxf(fmaxf(red[14 * 256 + ch],       red[14 * 256 + 64 + ch]),
                                fmaxf(red[14 * 256 + 128 + ch], red[14 * 256 + 192 + ch]));
                ob[13 * CCH + ch] = v * (1.0f / 128.0f) + m;
            }
        }
    }
}

// ======================================================================
extern "C" void kernel_launch(void* const* d_in, const int* in_sizes, int n_in,
                              void* d_out, int out_size)
{
    const float* feat = nullptr;
    const float* sco  = nullptr;
    const float* kc   = nullptr;
    for (int i = 0; i < n_in; ++i) {
        if (in_sizes[i] == NBAT * CCH * HW_)      feat = (const float*)d_in[i];
        else if (in_sizes[i] == NBAT * KPT * HW_) sco  = (const float*)d_in[i];
        else if (in_sizes[i] == NBAT * KPT)       kc   = (const float*)d_in[i];
    }
    float* out = (float*)d_out;

    horeid_feat_kernel<<<NBAT * 32, NTHR>>>(feat, sco, kc, out);
    (void)out_size;
}